// round 3
// baseline (speedup 1.0000x reference)
#include <cuda_runtime.h>
#include <cuda_bf16.h>
#include <cstdint>

#define NUM_BINS 5
#define DT_OFFSET 1
#define EV_PER_THREAD 4

// Each event row is [t, x, y, p] float32 -> load as float4.
// Output grid: (NUM_BINS*2, H, W) float32, scatter-add with bilinear
// temporal weights. Two atomicAdds per event; fwd bin = back bin + 1
// -> flat offset +2*H*W.

__device__ __forceinline__ void process_event(float4 ev, float bt, float inv_dt,
                                              int W, int H, int bin_stride,
                                              float* __restrict__ out)
{
    float t = ev.x;
    int   x = (int)ev.y;
    int   y = (int)ev.z;
    int pos = (ev.w > 0.0f) ? 1 : 0;

    float tn    = (t - bt) * inv_dt;              // (t - bt) / dt
    float bin_f = (float)(NUM_BINS - 1) * tn;
    float back  = floorf(bin_f);
    float fwd_w = bin_f - back;
    int back_i  = (int)back;

    float val_back = (1.0f - fwd_w) * tn;
    float val_fwd  = fwd_w * tn;

    int flat_back = ((back_i * 2 + pos) * H + y) * W + x;

    atomicAdd(&out[flat_back],              val_back);
    atomicAdd(&out[flat_back + bin_stride], val_fwd);
}

__global__ void __launch_bounds__(256)
voxel_grid_kernel(const float4* __restrict__ events,
                  int n,
                  const int* __restrict__ p_curr_time,
                  const int* __restrict__ p_delta_t,
                  const int* __restrict__ p_width,
                  const int* __restrict__ p_height,
                  float* __restrict__ out)
{
    const int curr_time = *p_curr_time;
    const int delta_t   = *p_delta_t;
    const int W         = *p_width;
    const int H         = *p_height;

    const float bt = (float)(curr_time - delta_t);
    const float inv_dt = 1.0f / (float)(delta_t + DT_OFFSET);
    const int bin_stride = 2 * H * W;   // pdim = 2

    int base = (blockIdx.x * blockDim.x + threadIdx.x) * EV_PER_THREAD;

    if (base + EV_PER_THREAD <= n) {
        // Full tile: batch all loads first (MLP), then compute + atomics.
        float4 ev[EV_PER_THREAD];
        #pragma unroll
        for (int j = 0; j < EV_PER_THREAD; j++)
            ev[j] = events[base + j];
        #pragma unroll
        for (int j = 0; j < EV_PER_THREAD; j++)
            process_event(ev[j], bt, inv_dt, W, H, bin_stride, out);
    } else {
        for (int idx = base; idx < n; idx++)
            process_event(events[idx], bt, inv_dt, W, H, bin_stride, out);
    }
}

extern "C" void kernel_launch(void* const* d_in, const int* in_sizes, int n_in,
                              void* d_out, int out_size)
{
    const float4* events = (const float4*)d_in[0];
    const int* curr_time = (const int*)d_in[1];
    const int* delta_t   = (const int*)d_in[2];
    const int* width     = (const int*)d_in[3];
    const int* height    = (const int*)d_in[4];
    float* out = (float*)d_out;

    int n = in_sizes[0] / 4;   // events has N*4 float elements

    // Zero-init the output grid (poisoned to 0xAA by the harness).
    cudaMemsetAsync(d_out, 0, (size_t)out_size * sizeof(float), 0);

    int threads = 256;
    int ev_per_block = threads * EV_PER_THREAD;
    int blocks = (n + ev_per_block - 1) / ev_per_block;
    voxel_grid_kernel<<<blocks, threads>>>(events, n,
                                           curr_time, delta_t, width, height,
                                           out);
}

// round 4
// speedup vs baseline: 1.3044x; 1.3044x over previous
#include <cuda_runtime.h>
#include <cuda_bf16.h>
#include <cstdint>

#define NUM_BINS 5
#define DT_OFFSET 1
#define EV_PER_THREAD 4

// Scratch sized for 1280x720 (the dataset shape): 2 pol * H*W cells * 8 floats.
// Layout: scratch[((pos*H + y)*W + x) * 8 + 2*back_i + {0,1}] = {val_back, val_fwd}
// Pairs sit at even float offsets -> 8-byte aligned -> one red.global.add.v2.f32
// per event instead of two scalar atomics.
#define SCRATCH_CAP (2 * 1280 * 720 * 8)
__device__ float g_scratch[SCRATCH_CAP];

__global__ void __launch_bounds__(256)
zero_scratch_kernel(int n4)
{
    int i = blockIdx.x * blockDim.x + threadIdx.x;
    int stride = gridDim.x * blockDim.x;
    float4* p = reinterpret_cast<float4*>(g_scratch);
    float4 z = make_float4(0.f, 0.f, 0.f, 0.f);
    for (; i < n4; i += stride) p[i] = z;
}

__device__ __forceinline__ void scatter_event_v2(float4 ev, float bt, float inv_dt,
                                                 int W, int H)
{
    float t = ev.x;
    int   x = (int)ev.y;
    int   y = (int)ev.z;
    int pos = (ev.w > 0.0f) ? 1 : 0;

    float tn    = (t - bt) * inv_dt;              // (t - bt) / dt
    float bin_f = (float)(NUM_BINS - 1) * tn;
    float back  = floorf(bin_f);
    float fwd_w = bin_f - back;
    int back_i  = (int)back;                      // 0..3 for this dataset

    float val_back = (1.0f - fwd_w) * tn;
    float val_fwd  = fwd_w * tn;

    int pc   = (pos * H + y) * W + x;
    float* addr = &g_scratch[pc * 8 + back_i * 2];
    asm volatile("red.global.add.v2.f32 [%0], {%1, %2};"
                 :: "l"(addr), "f"(val_back), "f"(val_fwd) : "memory");
}

__global__ void __launch_bounds__(256)
voxel_scatter_kernel(const float4* __restrict__ events,
                     int n,
                     const int* __restrict__ p_curr_time,
                     const int* __restrict__ p_delta_t,
                     const int* __restrict__ p_width,
                     const int* __restrict__ p_height)
{
    const int curr_time = *p_curr_time;
    const int delta_t   = *p_delta_t;
    const int W         = *p_width;
    const int H         = *p_height;

    const float bt = (float)(curr_time - delta_t);
    const float inv_dt = 1.0f / (float)(delta_t + DT_OFFSET);

    int base = (blockIdx.x * blockDim.x + threadIdx.x) * EV_PER_THREAD;

    if (base + EV_PER_THREAD <= n) {
        float4 ev[EV_PER_THREAD];
        #pragma unroll
        for (int j = 0; j < EV_PER_THREAD; j++)
            ev[j] = events[base + j];
        #pragma unroll
        for (int j = 0; j < EV_PER_THREAD; j++)
            scatter_event_v2(ev[j], bt, inv_dt, W, H);
    } else {
        for (int idx = base; idx < n; idx++)
            scatter_event_v2(events[idx], bt, inv_dt, W, H);
    }
}

// Fold 8 scratch slots per (pol,y,x) cell into the 5 output bins.
// out[(2b+pos)*plane + c] = slot[b].back + slot[b-1].fwd
__global__ void __launch_bounds__(256)
gather_kernel(float* __restrict__ out, int plane /* H*W */)
{
    int pc = blockIdx.x * blockDim.x + threadIdx.x;
    int ncells = 2 * plane;
    if (pc >= ncells) return;

    const float4* s = reinterpret_cast<const float4*>(g_scratch) + pc * 2;
    float4 lo = s[0];   // slot0.back, slot0.fwd, slot1.back, slot1.fwd
    float4 hi = s[1];   // slot2.back, slot2.fwd, slot3.back, slot3.fwd

    int pos = (pc >= plane) ? 1 : 0;
    int c   = pc - pos * plane;
    float* o = out + pos * plane + c;
    const int bs = 2 * plane;           // bin stride in output

    o[0 * bs] = lo.x;                   // bin0: back(slot0)
    o[1 * bs] = lo.z + lo.y;            // bin1: back(1) + fwd(0)
    o[2 * bs] = hi.x + lo.w;            // bin2: back(2) + fwd(1)
    o[3 * bs] = hi.z + hi.y;            // bin3: back(3) + fwd(2)
    o[4 * bs] = hi.w;                   // bin4: fwd(3)
}

// ---- Fallback (arbitrary dims): direct scalar-atomic path ----
__device__ __forceinline__ void process_event_direct(float4 ev, float bt, float inv_dt,
                                                     int W, int H, int bin_stride,
                                                     float* __restrict__ out)
{
    float t = ev.x;
    int   x = (int)ev.y;
    int   y = (int)ev.z;
    int pos = (ev.w > 0.0f) ? 1 : 0;

    float tn    = (t - bt) * inv_dt;
    float bin_f = (float)(NUM_BINS - 1) * tn;
    float back  = floorf(bin_f);
    float fwd_w = bin_f - back;
    int back_i  = (int)back;

    float val_back = (1.0f - fwd_w) * tn;
    float val_fwd  = fwd_w * tn;

    int flat_back = ((back_i * 2 + pos) * H + y) * W + x;
    atomicAdd(&out[flat_back],              val_back);
    atomicAdd(&out[flat_back + bin_stride], val_fwd);
}

__global__ void __launch_bounds__(256)
voxel_grid_direct_kernel(const float4* __restrict__ events, int n,
                         const int* __restrict__ p_curr_time,
                         const int* __restrict__ p_delta_t,
                         const int* __restrict__ p_width,
                         const int* __restrict__ p_height,
                         float* __restrict__ out)
{
    const int curr_time = *p_curr_time;
    const int delta_t   = *p_delta_t;
    const int W         = *p_width;
    const int H         = *p_height;
    const float bt = (float)(curr_time - delta_t);
    const float inv_dt = 1.0f / (float)(delta_t + DT_OFFSET);
    const int bin_stride = 2 * H * W;

    int base = (blockIdx.x * blockDim.x + threadIdx.x) * EV_PER_THREAD;
    if (base + EV_PER_THREAD <= n) {
        float4 ev[EV_PER_THREAD];
        #pragma unroll
        for (int j = 0; j < EV_PER_THREAD; j++) ev[j] = events[base + j];
        #pragma unroll
        for (int j = 0; j < EV_PER_THREAD; j++)
            process_event_direct(ev[j], bt, inv_dt, W, H, bin_stride, out);
    } else {
        for (int idx = base; idx < n; idx++)
            process_event_direct(events[idx], bt, inv_dt, W, H, bin_stride, out);
    }
}

extern "C" void kernel_launch(void* const* d_in, const int* in_sizes, int n_in,
                              void* d_out, int out_size)
{
    const float4* events = (const float4*)d_in[0];
    const int* curr_time = (const int*)d_in[1];
    const int* delta_t   = (const int*)d_in[2];
    const int* width     = (const int*)d_in[3];
    const int* height    = (const int*)d_in[4];
    float* out = (float*)d_out;

    int n = in_sizes[0] / 4;   // events has N*4 float elements

    // out_size = NUM_BINS*2*H*W  ->  plane = H*W
    int plane = out_size / (NUM_BINS * 2);
    int scratch_floats = 2 * plane * 8;

    const int threads = 256;
    int ev_per_block = threads * EV_PER_THREAD;
    int ev_blocks = (n + ev_per_block - 1) / ev_per_block;

    if (scratch_floats <= SCRATCH_CAP) {
        // 1) zero scratch
        int n4 = scratch_floats / 4;
        int zb = (n4 + threads - 1) / threads;
        if (zb > 4096) zb = 4096;
        zero_scratch_kernel<<<zb, threads>>>(n4);
        // 2) scatter with one v2 red per event
        voxel_scatter_kernel<<<ev_blocks, threads>>>(events, n,
                                                     curr_time, delta_t,
                                                     width, height);
        // 3) gather scratch -> out (fully writes out; no memset needed)
        int ncells = 2 * plane;
        int gb = (ncells + threads - 1) / threads;
        gather_kernel<<<gb, threads>>>(out, plane);
    } else {
        cudaMemsetAsync(d_out, 0, (size_t)out_size * sizeof(float), 0);
        voxel_grid_direct_kernel<<<ev_blocks, threads>>>(events, n,
                                                         curr_time, delta_t,
                                                         width, height, out);
    }
}